// round 4
// baseline (speedup 1.0000x reference)
#include <cuda_runtime.h>

#define NVOX 65536
#define CCH  64
#define NHEAD 4
#define HD   16
#define KVOL 125
#define NPAIR 1048576

// Scratch (static device globals per harness rules)
__device__ __align__(16) float g_nq[NVOX * CCH];
__device__ __align__(16) float g_nk[NVOX * CCH];
__device__ __align__(16) float g_v [NVOX * CCH];
__device__ __align__(16) float g_agg[NVOX * CCH];
__device__ __align__(16) float g_npos[KVOL * CCH];

// ---------------------------------------------------------------------------
// Kernel 0: zero the scatter accumulator + normalize pos_enc
// grid = 4096 (zero) + 32 (pos_enc), block = 256
// ---------------------------------------------------------------------------
__global__ void __launch_bounds__(256) prep_kernel(const float* __restrict__ pos_enc)
{
    int b = blockIdx.x;
    int tid = threadIdx.x;
    if (b < 4096) {
        // 4096 blocks * 256 threads * 1 float4 = NVOX*CCH floats
        ((float4*)g_agg)[b * 256 + tid] = make_float4(0.f, 0.f, 0.f, 0.f);
    } else {
        int t2 = (b - 4096) * 256 + tid;        // one thread per (kvol, h, d)
        if (t2 < KVOL * NHEAD * HD) {
            float v = pos_enc[t2];
            float ss = v * v;
            // reduce over d (16 consecutive lanes, 16-aligned within warp)
            ss += __shfl_xor_sync(0xffffffffu, ss, 1);
            ss += __shfl_xor_sync(0xffffffffu, ss, 2);
            ss += __shfl_xor_sync(0xffffffffu, ss, 4);
            ss += __shfl_xor_sync(0xffffffffu, ss, 8);
            float n = sqrtf(ss);
            g_npos[t2] = v / fmaxf(n, 1e-12f);
        }
    }
}

// ---------------------------------------------------------------------------
// Kernel 1: fused QKV projection + per-head L2 normalize (q,k only)
// grid = (1024, 3) : blockIdx.y selects matrix (0=Q,1=K,2=V)
// block = 256 threads = 16x16, each thread computes a 4x4 (row x chan) tile
// of a 64-row slab.
// ---------------------------------------------------------------------------
__global__ void __launch_bounds__(256) qkv_kernel(
    const float* __restrict__ x,
    const float* __restrict__ Wq, const float* __restrict__ bq,
    const float* __restrict__ Wk, const float* __restrict__ bk,
    const float* __restrict__ Wv, const float* __restrict__ bv)
{
    __shared__ __align__(16) float Ws[64 * 64];
    __shared__ __align__(16) float xs[64 * 65];   // xs[row][k], pad 65

    const int m = blockIdx.y;
    const float* __restrict__ W    = (m == 0) ? Wq : (m == 1) ? Wk : Wv;
    const float* __restrict__ bias = (m == 0) ? bq : (m == 1) ? bk : bv;
    float* __restrict__ outp       = (m == 0) ? g_nq : (m == 1) ? g_nk : g_v;

    const int rbase = blockIdx.x * 64;
    const int tid = threadIdx.x;

    #pragma unroll
    for (int i = 0; i < 16; i++)
        Ws[tid + i * 256] = W[tid + i * 256];
    #pragma unroll
    for (int i = 0; i < 16; i++) {
        int idx = tid + i * 256;
        int row = idx >> 6, k = idx & 63;
        xs[row * 65 + k] = x[(rbase + row) * 64 + k];
    }
    __syncthreads();

    const int tc = tid & 15;     // channel tile: channels tc*4 .. tc*4+3
    const int tr = tid >> 4;     // row tile:     rows     tr*4 .. tr*4+3

    float acc[4][4] = {};
    #pragma unroll
    for (int k = 0; k < 64; k++) {
        float4 w4 = *(const float4*)&Ws[k * 64 + tc * 4];
        #pragma unroll
        for (int j = 0; j < 4; j++) {
            float a = xs[(tr * 4 + j) * 65 + k];
            acc[j][0] += a * w4.x;
            acc[j][1] += a * w4.y;
            acc[j][2] += a * w4.z;
            acc[j][3] += a * w4.w;
        }
    }

    float4 bvec = *(const float4*)&bias[tc * 4];
    #pragma unroll
    for (int j = 0; j < 4; j++) {
        float v0 = acc[j][0] + bvec.x;
        float v1 = acc[j][1] + bvec.y;
        float v2 = acc[j][2] + bvec.z;
        float v3 = acc[j][3] + bvec.w;
        if (m != 2) {
            // per-head (16 channels = 4 consecutive tc) L2 normalize
            float ss = v0 * v0 + v1 * v1 + v2 * v2 + v3 * v3;
            ss += __shfl_xor_sync(0xffffffffu, ss, 1);
            ss += __shfl_xor_sync(0xffffffffu, ss, 2);
            float scale = 1.0f / fmaxf(sqrtf(ss), 1e-12f);
            v0 *= scale; v1 *= scale; v2 *= scale; v3 *= scale;
        }
        int row = rbase + tr * 4 + j;
        *(float4*)&outp[row * 64 + tc * 4] = make_float4(v0, v1, v2, v3);
    }
}

// ---------------------------------------------------------------------------
// Kernel 2: per-pair cosine attention + scatter (the dominant kernel)
// 16 lanes per pair; lane l owns channels [4l, 4l+4) i.e. head l>>2.
// block = 256 threads = 16 pairs; grid = 65536
// ---------------------------------------------------------------------------
__global__ void __launch_bounds__(256) pairs_kernel(const int* __restrict__ kq)
{
    const int tid = threadIdx.x;
    const int p = blockIdx.x * 16 + (tid >> 4);
    const int l = tid & 15;

    const unsigned i0 = (unsigned)kq[p];           // in_idx*125 + kern_idx
    const int      o  = kq[NPAIR + p];             // out_idx (query voxel)
    const unsigned in  = i0 / 125u;
    const unsigned kid = i0 - in * 125u;

    const float4 q  = *(const float4*)&g_nq[(unsigned)o * 64u + l * 4];
    const float4 kk = *(const float4*)&g_nk[in * 64u + l * 4];
    const float4 pe = *(const float4*)&g_npos[kid * 64u + l * 4];

    float s = q.x * (kk.x + pe.x) + q.y * (kk.y + pe.y)
            + q.z * (kk.z + pe.z) + q.w * (kk.w + pe.w);
    // reduce over the 4 lanes of this head (xor 1,2 stays in the aligned quad)
    s += __shfl_xor_sync(0xffffffffu, s, 1);
    s += __shfl_xor_sync(0xffffffffu, s, 2);

    const float4 vv = *(const float4*)&g_v[in * 64u + l * 4];
    float* dst = &g_agg[(unsigned)o * 64u + l * 4];
    asm volatile("red.global.add.v4.f32 [%0], {%1, %2, %3, %4};"
                 :: "l"(dst), "f"(s * vv.x), "f"(s * vv.y),
                    "f"(s * vv.z), "f"(s * vv.w)
                 : "memory");
}

// ---------------------------------------------------------------------------
// Kernel 3: output projection + bias + residual
// Same tiling as qkv_kernel, single matrix, reads g_agg, adds x, writes d_out.
// ---------------------------------------------------------------------------
__global__ void __launch_bounds__(256) out_kernel(
    const float* __restrict__ Wo, const float* __restrict__ bo,
    const float* __restrict__ x, float* __restrict__ out)
{
    __shared__ __align__(16) float Ws[64 * 64];
    __shared__ __align__(16) float xs[64 * 65];

    const int rbase = blockIdx.x * 64;
    const int tid = threadIdx.x;

    #pragma unroll
    for (int i = 0; i < 16; i++)
        Ws[tid + i * 256] = Wo[tid + i * 256];
    #pragma unroll
    for (int i = 0; i < 16; i++) {
        int idx = tid + i * 256;
        int row = idx >> 6, k = idx & 63;
        xs[row * 65 + k] = g_agg[(rbase + row) * 64 + k];
    }
    __syncthreads();

    const int tc = tid & 15;
    const int tr = tid >> 4;

    float acc[4][4] = {};
    #pragma unroll
    for (int k = 0; k < 64; k++) {
        float4 w4 = *(const float4*)&Ws[k * 64 + tc * 4];
        #pragma unroll
        for (int j = 0; j < 4; j++) {
            float a = xs[(tr * 4 + j) * 65 + k];
            acc[j][0] += a * w4.x;
            acc[j][1] += a * w4.y;
            acc[j][2] += a * w4.z;
            acc[j][3] += a * w4.w;
        }
    }

    float4 bvec = *(const float4*)&bo[tc * 4];
    #pragma unroll
    for (int j = 0; j < 4; j++) {
        int row = rbase + tr * 4 + j;
        float4 res = *(const float4*)&x[row * 64 + tc * 4];
        float4 ov;
        ov.x = acc[j][0] + bvec.x + res.x;
        ov.y = acc[j][1] + bvec.y + res.y;
        ov.z = acc[j][2] + bvec.z + res.z;
        ov.w = acc[j][3] + bvec.w + res.w;
        *(float4*)&out[row * 64 + tc * 4] = ov;
    }
}

// ---------------------------------------------------------------------------
// Launch. Input order (metadata): x, Wq, bq, Wk, bk, Wv, bv, Wo, bo,
//                                 pos_enc, kq_map
// ---------------------------------------------------------------------------
extern "C" void kernel_launch(void* const* d_in, const int* in_sizes, int n_in,
                              void* d_out, int out_size)
{
    const float* x       = (const float*)d_in[0];
    const float* Wq      = (const float*)d_in[1];
    const float* bq      = (const float*)d_in[2];
    const float* Wk      = (const float*)d_in[3];
    const float* bk      = (const float*)d_in[4];
    const float* Wv      = (const float*)d_in[5];
    const float* bv      = (const float*)d_in[6];
    const float* Wo      = (const float*)d_in[7];
    const float* bo      = (const float*)d_in[8];
    const float* pos_enc = (const float*)d_in[9];
    const int*   kq      = (const int*)d_in[10];
    float* out = (float*)d_out;

    prep_kernel<<<4096 + 32, 256>>>(pos_enc);
    qkv_kernel<<<dim3(NVOX / 64, 3), 256>>>(x, Wq, bq, Wk, bk, Wv, bv);
    pairs_kernel<<<NPAIR / 16, 256>>>(kq);
    out_kernel<<<NVOX / 64, 256>>>(Wo, bo, x, out);
}